// round 17
// baseline (speedup 1.0000x reference)
#include <cuda_runtime.h>
#include <cuda_fp16.h>
#include <cstdint>

// DynamicPooling R17: reuse sweeps restructured around a cp.async SMEM ring.
// Diagnosis: reuse loops were L2-latency-bound (IPC 0.33) with only ~48B in
// flight per warp. Fix: 4-stage x 16-row (8KB) cp.async ring -> ~24KB/block
// in flight, decoupling memory service from compute. Compute = R14 scalar
// math reading y from SMEM. Fill kernel + fork-join schedule unchanged.
// B=64, N=4096, D=256. x f32 [B,N,D], m f32 [B,N,1]. Out: w [B,N], s [B,D].

namespace {
constexpr int Bb = 64;
constexpr int Nn = 4096;
constexpr int Dd = 256;
constexpr int NCHUNK = 32;            // N-chunks per batch
constexpr int ROWS = Nn / NCHUNK;     // 128 rows per block
constexpr int WARPS = 8;
constexpr int RPW = ROWS / WARPS;     // 16 rows per warp
constexpr int GRP = 16;               // batches per group
constexpr int NGRP = Bb / GRP;        // 4 groups
constexpr int PFF = 3;                // prefetch depth, fill (DRAM, f32)
constexpr int STG_ROWS = 16;          // rows per ring stage
constexpr int NSTG = ROWS / STG_ROWS; // 8 stages per tile
constexpr int SLOTS = 4;              // ring slots (3 in flight)
constexpr int STG_BYTES = STG_ROWS * Dd * 2;  // 8192
}

__device__ __half g_y[(size_t)Bb * Nn * Dd];  // fp16 cache of m*x (128MB)
__device__ float g_part[Bb * NCHUNK * Dd];    // unnormalized sigma partials
__device__ float g_Z[Bb * NCHUNK];            // per-chunk mass
__device__ float g_b[Bb * Nn];

namespace {
struct StreamKit {
    cudaStream_t s1;
    cudaEvent_t ev_root;
    cudaEvent_t ev_fill[NGRP];
    StreamKit() {
        cudaStreamCreateWithFlags(&s1, cudaStreamNonBlocking);
        cudaEventCreateWithFlags(&ev_root, cudaEventDisableTiming);
        for (int i = 0; i < NGRP; i++)
            cudaEventCreateWithFlags(&ev_fill[i], cudaEventDisableTiming);
    }
};
StreamKit g_kit;
}

__device__ __forceinline__ unsigned int pack2h(float a, float b) {
    __half2 h = __floats2half2_rn(a, b);
    return *reinterpret_cast<unsigned int*>(&h);
}
__device__ __forceinline__ float2 unpack2h(unsigned int u) {
    return __half22float2(*reinterpret_cast<__half2*>(&u));
}

// ---------------- fill kernel: y = m*x (fp16) + sigma1 partials -----------
__global__ void __launch_bounds__(256, 4) fill_kernel(
    const float* x, const float* __restrict__ m, int b0) {
    const int b = b0 + blockIdx.y;
    const int c = blockIdx.x;
    const int t = threadIdx.x, w = t >> 5, l = t & 31;
    const int n0 = c * ROWS;

    __shared__ float m_sh[ROWS];
    __shared__ float sm_acc[WARPS * Dd];

    if (t < ROWS) m_sh[t] = m[b * Nn + n0 + t];
    __syncthreads();

    const size_t rowbase = (size_t)b * Nn + n0;
    const float* xb = x + rowbase * Dd;
    const int d0 = l << 2;

    float4 pa[PFF], pb[PFF];
#pragma unroll
    for (int j = 0; j < PFF; j++) {
        const float* xr = xb + (size_t)(w * RPW + j) * Dd;
        pa[j] = *reinterpret_cast<const float4*>(xr + d0);
        pb[j] = *reinterpret_cast<const float4*>(xr + 128 + d0);
    }

    float acc[8] = {0, 0, 0, 0, 0, 0, 0, 0};
#pragma unroll
    for (int i = 0; i < RPW; i++) {
        const int n = w * RPW + i;
        const float4 a0 = pa[i % PFF];
        const float4 a1 = pb[i % PFF];
        if (i + PFF < RPW) {
            const float* xn = xb + (size_t)(n + PFF) * Dd;
            pa[i % PFF] = *reinterpret_cast<const float4*>(xn + d0);
            pb[i % PFF] = *reinterpret_cast<const float4*>(xn + 128 + d0);
        }
        const float mn = m_sh[n];
        const float y0 = mn * a0.x, y1 = mn * a0.y, y2 = mn * a0.z, y3 = mn * a0.w;
        const float y4 = mn * a1.x, y5 = mn * a1.y, y6 = mn * a1.z, y7 = mn * a1.w;
        acc[0] += y0; acc[1] += y1; acc[2] += y2; acc[3] += y3;
        acc[4] += y4; acc[5] += y5; acc[6] += y6; acc[7] += y7;
        uint2 ua = make_uint2(pack2h(y0, y1), pack2h(y2, y3));
        uint2 ub = make_uint2(pack2h(y4, y5), pack2h(y6, y7));
        __half* yr = g_y + (rowbase + n) * Dd;
        *reinterpret_cast<uint2*>(yr + d0) = ua;
        *reinterpret_cast<uint2*>(yr + 128 + d0) = ub;
    }

    *reinterpret_cast<float4*>(&sm_acc[w * Dd + d0]) =
        make_float4(acc[0], acc[1], acc[2], acc[3]);
    *reinterpret_cast<float4*>(&sm_acc[w * Dd + 128 + d0]) =
        make_float4(acc[4], acc[5], acc[6], acc[7]);
    __syncthreads();

    float sig = 0.0f;
#pragma unroll
    for (int k = 0; k < WARPS; k++) sig += sm_acc[k * Dd + t];
    g_part[((size_t)b * NCHUNK + c) * Dd + t] = sig;
    if (t == 0) g_Z[b * NCHUNK + c] = (float)ROWS;  // uniform weights mass
}

// ------------- reuse kernel: cp.async ring + R14-style compute -----------
// FINAL=false: head-combine -> s; b += dot(s,y); next sigma partials.
// FINAL=true : head-combine -> s (write out_s); b-update only.
template <bool FINAL, bool ZEROB>
__global__ void __launch_bounds__(256, 4) reuse_kernel(
    const float* __restrict__ m, int b0, float* __restrict__ out_s) {
    const int b = b0 + blockIdx.y;
    const int c = blockIdx.x;
    const int t = threadIdx.x, w = t >> 5, l = t & 31;
    const int n0 = c * ROWS;

    __shared__ __align__(16) __half y_sh[SLOTS][STG_ROWS * Dd];  // 32 KB ring
    __shared__ float s_sh[Dd];
    __shared__ float m_sh[ROWS];
    __shared__ float b_sh[ROWS];
    __shared__ float sm_acc[WARPS * Dd];
    __shared__ float sm_Z[WARPS];
    __shared__ float red[256];
    __shared__ float hz[NCHUNK];

    {
        int gi = b * Nn + n0;
        if (t < ROWS) {
            m_sh[t] = m[gi + t];
            b_sh[t] = ZEROB ? 0.0f : g_b[gi + t];
        }
    }
    // head-combine: rebuild s from previous sweep's partials
    if (t < NCHUNK) hz[t] = g_Z[b * NCHUNK + t];
    __syncthreads();
    {
        float v = 0.0f, Zg = 0.0f;
#pragma unroll
        for (int k = 0; k < NCHUNK; k++) {
            v += g_part[((size_t)b * NCHUNK + k) * Dd + t];
            Zg += hz[k];
        }
        const float sigma = v / Zg;
        red[t] = sigma * sigma;
        __syncthreads();
#pragma unroll
        for (int s = 128; s > 0; s >>= 1) {
            if (t < s) red[t] += red[t + s];
            __syncthreads();
        }
        const float n2 = red[0];
        const float norm = sqrtf(n2);
        const float sv = (n2 / (1.0f + n2) / (norm + 1e-8f)) * sigma;
        s_sh[t] = sv;
        if (FINAL && c == 0 && out_s) out_s[b * Dd + t] = sv;
    }
    __syncthreads();

    const size_t rowbase = (size_t)b * Nn + n0;
    const char* ygl = reinterpret_cast<const char*>(g_y + rowbase * Dd);
    const int h0 = l << 3;  // lane owns 8 cols at h0

    // loop-invariant s in registers
    const float s0 = s_sh[h0],     s1 = s_sh[h0 + 1],
                s2 = s_sh[h0 + 2], s3 = s_sh[h0 + 3];
    const float s4 = s_sh[h0 + 4], s5 = s_sh[h0 + 5],
                s6 = s_sh[h0 + 6], s7 = s_sh[h0 + 7];

    // each thread copies 32 bytes per stage (2 x 16B cp.async)
    const int cpo = t * 32;  // byte offset within a stage (256*32 = 8192)

    // prologue: stages 0..2 in flight
#pragma unroll
    for (int st = 0; st < SLOTS - 1; st++) {
        unsigned int dst = (unsigned int)__cvta_generic_to_shared(
            &y_sh[st][0]) + cpo;
        const char* src = ygl + (size_t)st * STG_BYTES + cpo;
        asm volatile("cp.async.cg.shared.global [%0], [%1], 16;"
                     :: "r"(dst), "l"(src));
        asm volatile("cp.async.cg.shared.global [%0], [%1], 16;"
                     :: "r"(dst + 16), "l"(src + 16));
        asm volatile("cp.async.commit_group;");
    }

    float acc[8] = {0, 0, 0, 0, 0, 0, 0, 0};
    float Z = 0.0f;

#pragma unroll
    for (int st = 0; st < NSTG; st++) {
        asm volatile("cp.async.wait_group 2;");
        __syncthreads();   // stage st visible to all; stage st-1 fully consumed

        if (st + SLOTS - 1 < NSTG) {   // refill the slot consumed last iter
            const int nst = st + SLOTS - 1;
            unsigned int dst = (unsigned int)__cvta_generic_to_shared(
                &y_sh[nst & (SLOTS - 1)][0]) + cpo;
            const char* src = ygl + (size_t)nst * STG_BYTES + cpo;
            asm volatile("cp.async.cg.shared.global [%0], [%1], 16;"
                         :: "r"(dst), "l"(src));
            asm volatile("cp.async.cg.shared.global [%0], [%1], 16;"
                         :: "r"(dst + 16), "l"(src + 16));
        }
        asm volatile("cp.async.commit_group;");  // uniform group count per thread

        // compute: warp w handles stage rows w and w+8
#pragma unroll
        for (int rr = 0; rr < 2; rr++) {
            const int r = w + rr * 8;            // row within stage
            const int n = st * STG_ROWS + r;     // row within tile
            const uint4 u = *reinterpret_cast<const uint4*>(
                &y_sh[st & (SLOTS - 1)][r * Dd + h0]);
            const float2 f0 = unpack2h(u.x), f1 = unpack2h(u.y),
                         f2 = unpack2h(u.z), f3 = unpack2h(u.w);

            float dot = f0.x * s0 + f0.y * s1 + f1.x * s2 + f1.y * s3 +
                        f2.x * s4 + f2.y * s5 + f3.x * s6 + f3.y * s7;
#pragma unroll
            for (int o = 16; o > 0; o >>= 1)
                dot += __shfl_xor_sync(0xffffffffu, dot, o);

            const float bnew = b_sh[n] + dot;    // y already includes m
            if (l == 0) g_b[b * Nn + n0 + n] = bnew;

            if (!FINAL) {
                const float e = __expf(m_sh[n] * bnew);  // |logit| <= ~24: safe
                Z += e;
                acc[0] = fmaf(e, f0.x, acc[0]);
                acc[1] = fmaf(e, f0.y, acc[1]);
                acc[2] = fmaf(e, f1.x, acc[2]);
                acc[3] = fmaf(e, f1.y, acc[3]);
                acc[4] = fmaf(e, f2.x, acc[4]);
                acc[5] = fmaf(e, f2.y, acc[5]);
                acc[6] = fmaf(e, f3.x, acc[6]);
                acc[7] = fmaf(e, f3.y, acc[7]);
            }
        }
    }
    asm volatile("cp.async.wait_group 0;");

    if (!FINAL) {
        *reinterpret_cast<float4*>(&sm_acc[w * Dd + h0]) =
            make_float4(acc[0], acc[1], acc[2], acc[3]);
        *reinterpret_cast<float4*>(&sm_acc[w * Dd + h0 + 4]) =
            make_float4(acc[4], acc[5], acc[6], acc[7]);
        if (l == 0) sm_Z[w] = Z;
        __syncthreads();

        float sig = 0.0f;
#pragma unroll
        for (int k = 0; k < WARPS; k++) sig += sm_acc[k * Dd + t];
        g_part[((size_t)b * NCHUNK + c) * Dd + t] = sig;
        if (t == 0) {
            float Zb = 0.0f;
#pragma unroll
            for (int k = 0; k < WARPS; k++) Zb += sm_Z[k];
            g_Z[b * NCHUNK + c] = Zb;
        }
    }
}

// Final w = softmax(b) over N (no m factor). Exact 2-pass in-register.
__global__ void __launch_bounds__(256) final_softmax_kernel(float* __restrict__ out_w) {
    const int b = blockIdx.x, t = threadIdx.x;
    const float* bb = g_b + (size_t)b * Nn;

    float vals[16];
    float lmax = -3.4e38f;
#pragma unroll
    for (int i = 0; i < 16; i++) {
        vals[i] = bb[t + i * 256];
        lmax = fmaxf(lmax, vals[i]);
    }
    __shared__ float red[256];
    red[t] = lmax;
    __syncthreads();
#pragma unroll
    for (int s = 128; s > 0; s >>= 1) {
        if (t < s) red[t] = fmaxf(red[t], red[t + s]);
        __syncthreads();
    }
    const float gmax = red[0];
    __syncthreads();

    float lsum = 0.0f;
#pragma unroll
    for (int i = 0; i < 16; i++) {
        vals[i] = __expf(vals[i] - gmax);
        lsum += vals[i];
    }
    red[t] = lsum;
    __syncthreads();
#pragma unroll
    for (int s = 128; s > 0; s >>= 1) {
        if (t < s) red[t] += red[t + s];
        __syncthreads();
    }
    const float inv = 1.0f / red[0];
#pragma unroll
    for (int i = 0; i < 16; i++)
        out_w[(size_t)b * Nn + t + i * 256] = vals[i] * inv;
}

extern "C" void kernel_launch(void* const* d_in, const int* in_sizes, int n_in,
                              void* d_out, int out_size) {
    (void)in_sizes; (void)n_in; (void)out_size;
    const float* x = (const float*)d_in[0];
    const float* m = (const float*)d_in[1];
    float* out = (float*)d_out;
    float* out_w = out;             // [B, N]
    float* out_s = out + Bb * Nn;   // [B, D]

    const dim3 grid(NCHUNK, GRP);

    // Fork side stream into the capture.
    cudaEventRecord(g_kit.ev_root, 0);
    cudaStreamWaitEvent(g_kit.s1, g_kit.ev_root, 0);

    for (int g = 0; g < NGRP; ++g) {
        fill_kernel<<<grid, 256, 0, g_kit.s1>>>(x, m, g * GRP);
        cudaEventRecord(g_kit.ev_fill[g], g_kit.s1);
    }

    for (int g = 0; g < NGRP; ++g) {
        const int b0 = g * GRP;
        cudaStreamWaitEvent(0, g_kit.ev_fill[g], 0);
        reuse_kernel<false, true><<<grid, 256>>>(m, b0, nullptr);   // b1+sigma2
        reuse_kernel<false, false><<<grid, 256>>>(m, b0, nullptr);  // b2+sigma3
        reuse_kernel<true, false><<<grid, 256>>>(m, b0, out_s);     // s3+b3
    }
    final_softmax_kernel<<<Bb, 256>>>(out_w);  // w = softmax(b3)
}